// round 14
// baseline (speedup 1.0000x reference)
#include <cuda_runtime.h>
#include <cuda_fp16.h>
#include <float.h>

#define VQ_D      64
#define KCODES    512
#define M_TILE    128
#define NTHREADS  256
#define NROWS_MAX 524288
#define TAU       1e-3f

typedef unsigned int       u32;
typedef unsigned long long u64;

// ---------------- global scratch (static: no allocation) ----------------
__device__ int    g_flag_count;
__device__ int    g_flag_rows[NROWS_MAX];
__device__ float  g_loss_row[NROWS_MAX];
__device__ double g_partials[256];

// ---------------- smem layout of main kernel (bytes) ----------------
#define SM_BHI   0                        // 512*128 = 65536  B hi fp16, SW128
#define SM_BLO   (SM_BHI + KCODES*128)    // 65536
#define SM_AHI   (SM_BLO + KCODES*128)    // 131072  128*128
#define SM_ALO   (SM_AHI + M_TILE*128)    // 147456
#define XSTRIDE  272                      // 256B row + 16B pad (bank spread)
#define SM_XSTG  (SM_ALO + M_TILE*128)    // 163840  128*272 = 34816 x stage
#define SM_EE    (SM_XSTG + M_TILE*XSTRIDE) // 198656  512 f32
#define SM_SB    (SM_EE  + KCODES*4)      // 200704  2*128 f32 best
#define SM_SS    (SM_SB  + 2*M_TILE*4)    // 201728  2*128 f32 second
#define SM_SI    (SM_SS  + 2*M_TILE*4)    // 202752  2*128 i32 idx
#define SM_TOTAL (SM_SI  + 2*M_TILE*4 + 64)   // ~203.8 KB

// ---------------- helpers ----------------
__device__ __forceinline__ u32 smem_u32_base(const void* p) {
    u32 a;
    asm("{ .reg .u64 t; cvta.to.shared.u64 t, %1; cvt.u32.u64 %0, t; }"
        : "=r"(a) : "l"(p));
    return a;
}
// swizzled byte offset for 128B-row tiles (SW128: bits[6:4] ^= bits[9:7])
__device__ __forceinline__ u32 swofs(u32 row, u32 off) {
    u32 b = row * 128u + off;
    return b ^ ((b >> 3) & 0x70u);
}
__device__ __forceinline__ void ldsm_x4(u32& r0, u32& r1, u32& r2, u32& r3, u32 addr) {
    asm volatile("ldmatrix.sync.aligned.m8n8.x4.shared.b16 {%0,%1,%2,%3}, [%4];"
        : "=r"(r0), "=r"(r1), "=r"(r2), "=r"(r3) : "r"(addr));
}
__device__ __forceinline__ void mma16816(float* c, const u32* a, u32 b0, u32 b1) {
    asm volatile("mma.sync.aligned.m16n8k16.row.col.f32.f16.f16.f32 "
        "{%0,%1,%2,%3}, {%4,%5,%6,%7}, {%8,%9}, {%0,%1,%2,%3};"
        : "+f"(c[0]), "+f"(c[1]), "+f"(c[2]), "+f"(c[3])
        : "r"(a[0]), "r"(a[1]), "r"(a[2]), "r"(a[3]), "r"(b0), "r"(b1));
}
__device__ __forceinline__ void cp16(u32 dst, const void* src) {
    asm volatile("cp.async.cg.shared.global [%0], [%1], 16;"
        :: "r"(dst), "l"(src) : "memory");
}
#define CP_COMMIT() asm volatile("cp.async.commit_group;" ::: "memory")
#define CP_WAIT0()  asm volatile("cp.async.wait_group 0;" ::: "memory")

// fp16 Dekker split: v = (float)hi + (float)lo + O(2^-22 |v|)
__device__ __forceinline__ void split16(float v, __half& hi, __half& lo) {
    hi = __float2half_rn(v);
    lo = __float2half_rn(v - __half2float(hi));
}
// packed f32x2 (exact replica of the R8 arithmetic for the fixup path)
__device__ __forceinline__ u64 fma2(u64 a, u64 b, u64 c) {
    u64 d;
    asm("fma.rn.f32x2 %0, %1, %2, %3;" : "=l"(d) : "l"(a), "l"(b), "l"(c));
    return d;
}
__device__ __forceinline__ u64 add2(u64 a, u64 b) {
    u64 d;
    asm("add.rn.f32x2 %0, %1, %2;" : "=l"(d) : "l"(a), "l"(b));
    return d;
}
__device__ __forceinline__ float2 u2f(u64 a) {
    float2 r;
    r.x = __uint_as_float((unsigned int)(a & 0xffffffffull));
    r.y = __uint_as_float((unsigned int)(a >> 32));
    return r;
}

// ---------------------------------------------------------------------------
__global__ void vq_init_kernel() { g_flag_count = 0; }

// ---------------------------------------------------------------------------
// Kernel 1: tensor-core score pass (fp16 split, 3 terms), cp.async-pipelined.
// Score = ||e||^2 - 2<x,e>  (xx dropped: argmin-invariant; near-ties with the
// reference's rounded distance are caught by the margin flag + exact fixup).
// ---------------------------------------------------------------------------
__global__ void __launch_bounds__(NTHREADS, 1)
vq_main_kernel(const float* __restrict__ x,
               const float* __restrict__ cb,
               float* __restrict__ out,
               int n)
{
    extern __shared__ char sm[];
    const u32 su  = smem_u32_base(sm);
    const int tid = threadIdx.x;
    const int w   = tid >> 5;
    const int lid = tid & 31;
    const int wm  = w & 3;        // M chunk: rows wm*32..+32
    const int wn  = w >> 2;       // N half:  codes wn*256..+256

    float* sh_ee = (float*)(sm + SM_EE);
    float* sh_b  = (float*)(sm + SM_SB);
    float* sh_s  = (float*)(sm + SM_SS);
    int*   sh_i  = (int*)  (sm + SM_SI);

    // ---- codebook: split into B_hi/B_lo fp16 (SW128) + fp32 ||e||^2 ----
    for (int kk = tid; kk < KCODES; kk += NTHREADS) {
        const float4* e4 = (const float4*)(cb + (size_t)kk * VQ_D);
        float a0 = 0.f, a1 = 0.f, a2 = 0.f, a3 = 0.f;
        #pragma unroll
        for (int j = 0; j < 16; j++) {
            float4 v = e4[j];
            __half h0, h1, h2, h3, l0h, l1h, l2h, l3h;
            split16(v.x, h0, l0h); split16(v.y, h1, l1h);
            split16(v.z, h2, l2h); split16(v.w, h3, l3h);
            u32 b = swofs((u32)kk, (u32)j * 8u);
            *(__half2*)(sm + SM_BHI + b)     = __halves2half2(h0, h1);
            *(__half2*)(sm + SM_BHI + b + 4) = __halves2half2(h2, h3);
            *(__half2*)(sm + SM_BLO + b)     = __halves2half2(l0h, l1h);
            *(__half2*)(sm + SM_BLO + b + 4) = __halves2half2(l2h, l3h);
            a0 = fmaf(v.x, v.x, a0); a1 = fmaf(v.y, v.y, a1);
            a2 = fmaf(v.z, v.z, a2); a3 = fmaf(v.w, v.w, a3);
        }
        sh_ee[kk] = __fadd_rn(__fadd_rn(a0, a1), __fadd_rn(a2, a3));
    }

    // per-lane ldmatrix address components
    const u32 arow = (u32)(lid & 7) + ((u32)(lid >> 3) & 1u) * 8u;
    const u32 aoff = ((u32)(lid >> 4) & 1u) * 16u;
    const u32 brow = (u32)(lid & 7) + ((u32)(lid >> 4) & 1u) * 8u;
    const u32 boff = ((u32)(lid >> 3) & 1u) * 16u;
    const int g = lid >> 2, t = lid & 3;

    // prefetch mapping: thread -> row tid/2, d-half tid&1
    const int pr = tid >> 1, ph = tid & 1;
    const u32 stg_dst = su + SM_XSTG + (u32)pr * XSTRIDE + (u32)ph * 128u;

    const int ntiles = n / M_TILE;

    // ---- prologue: stage first tile's x ----
    {
        int t0 = blockIdx.x;
        if (t0 < ntiles) {
            const float* src = x + ((size_t)t0 * M_TILE + pr) * VQ_D + ph * 32;
            #pragma unroll
            for (int j = 0; j < 8; j++) cp16(stg_dst + j * 16u, src + j * 4);
        }
        CP_COMMIT();
    }

    for (int tile = blockIdx.x; tile < ntiles; tile += gridDim.x) {
        CP_WAIT0();
        __syncthreads();   // stage ready for all; prev-tile smem readers done

        // ---- convert staged x -> A_hi/A_lo (SW128) ----
        {
            const float4* xp = (const float4*)(sm + SM_XSTG + pr * XSTRIDE + ph * 128);
            #pragma unroll
            for (int j = 0; j < 8; j++) {
                float4 v = xp[j];
                __half h0, h1, h2, h3, l0h, l1h, l2h, l3h;
                split16(v.x, h0, l0h); split16(v.y, h1, l1h);
                split16(v.z, h2, l2h); split16(v.w, h3, l3h);
                u32 b = swofs((u32)pr, (u32)(ph * 64 + j * 8));
                *(__half2*)(sm + SM_AHI + b)     = __halves2half2(h0, h1);
                *(__half2*)(sm + SM_AHI + b + 4) = __halves2half2(h2, h3);
                *(__half2*)(sm + SM_ALO + b)     = __halves2half2(l0h, l1h);
                *(__half2*)(sm + SM_ALO + b + 4) = __halves2half2(l2h, l3h);
            }
        }
        __syncthreads();   // A ready; stage free for next prefetch

        // ---- prefetch next tile's x under the MMA/epilogue ----
        {
            int nxt = tile + gridDim.x;
            if (nxt < ntiles) {
                const float* src = x + ((size_t)nxt * M_TILE + pr) * VQ_D + ph * 32;
                #pragma unroll
                for (int j = 0; j < 8; j++) cp16(stg_dst + j * 16u, src + j * 4);
            }
            CP_COMMIT();
        }

        // ---- A fragments for this warp's 32 rows (hi & lo), all 4 k-chunks ----
        u32 ahi[2][4][4], alo[2][4][4];
        #pragma unroll
        for (int ms = 0; ms < 2; ms++) {
            #pragma unroll
            for (int k = 0; k < 4; k++) {
                u32 o = swofs((u32)(wm * 32 + ms * 16) + arow, (u32)k * 32u + aoff);
                ldsm_x4(ahi[ms][k][0], ahi[ms][k][1], ahi[ms][k][2], ahi[ms][k][3],
                        su + SM_AHI + o);
                ldsm_x4(alo[ms][k][0], alo[ms][k][1], alo[ms][k][2], alo[ms][k][3],
                        su + SM_ALO + o);
            }
        }

        float best[4] = {FLT_MAX, FLT_MAX, FLT_MAX, FLT_MAX};
        float sec [4] = {FLT_MAX, FLT_MAX, FLT_MAX, FLT_MAX};
        int   bidx[4] = {0, 0, 0, 0};

        #pragma unroll 1
        for (int chunk = 0; chunk < 4; chunk++) {
            const int nbase = wn * 256 + chunk * 64;
            float acc[2][8][4];
            #pragma unroll
            for (int ms = 0; ms < 2; ms++)
                #pragma unroll
                for (int j = 0; j < 8; j++)
                    #pragma unroll
                    for (int q = 0; q < 4; q++) acc[ms][j][q] = 0.f;

            #pragma unroll
            for (int k = 0; k < 4; k++) {
                u32 bh0[8], bh1[8], bl0[8], bl1[8];
                #pragma unroll
                for (int gi = 0; gi < 4; gi++) {
                    u32 o = swofs((u32)(nbase + gi * 16) + brow, (u32)k * 32u + boff);
                    ldsm_x4(bh0[2*gi], bh1[2*gi], bh0[2*gi+1], bh1[2*gi+1], su + SM_BHI + o);
                    ldsm_x4(bl0[2*gi], bl1[2*gi], bl0[2*gi+1], bl1[2*gi+1], su + SM_BLO + o);
                }
                #pragma unroll
                for (int ms = 0; ms < 2; ms++) {
                    #pragma unroll
                    for (int j = 0; j < 8; j++) {
                        mma16816(acc[ms][j], ahi[ms][k], bh0[j], bh1[j]);  // hi*hi
                        mma16816(acc[ms][j], alo[ms][k], bh0[j], bh1[j]);  // lo*hi
                        mma16816(acc[ms][j], ahi[ms][k], bl0[j], bl1[j]);  // hi*lo
                    }
                }
            }

            // ---- epilogue: score = ee - 2*dot, top-2 tracking ----
            #pragma unroll
            for (int ms = 0; ms < 2; ms++) {
                const int ri = ms * 2;
                #pragma unroll
                for (int j = 0; j < 8; j++) {
                    const int c0 = nbase + j * 8 + 2 * t;
                    float2 ee = *(const float2*)(&sh_ee[c0]);
                    float d00 = fmaf(acc[ms][j][0], -2.f, ee.x);
                    float d01 = fmaf(acc[ms][j][1], -2.f, ee.y);
                    float d10 = fmaf(acc[ms][j][2], -2.f, ee.x);
                    float d11 = fmaf(acc[ms][j][3], -2.f, ee.y);
                    #define UPD(r_, d_, c_) \
                        if ((d_) < best[r_]) { sec[r_] = best[r_]; best[r_] = (d_); bidx[r_] = (c_); } \
                        else sec[r_] = fminf(sec[r_], (d_));
                    UPD(ri,     d00, c0); UPD(ri,     d01, c0 + 1);
                    UPD(ri + 1, d10, c0); UPD(ri + 1, d11, c0 + 1);
                    #undef UPD
                }
            }
        }

        // ---- intra-warp merge over the 4 t-lanes sharing each row ----
        #pragma unroll
        for (int off = 1; off <= 2; off <<= 1) {
            #pragma unroll
            for (int ri = 0; ri < 4; ri++) {
                float ob = __shfl_xor_sync(0xffffffffu, best[ri], off);
                float os = __shfl_xor_sync(0xffffffffu, sec[ri],  off);
                int   oi = __shfl_xor_sync(0xffffffffu, bidx[ri], off);
                bool take = (ob < best[ri]) || (ob == best[ri] && oi < bidx[ri]);
                float loser = take ? best[ri] : ob;
                sec[ri] = fminf(loser, fminf(sec[ri], os));
                if (take) { best[ri] = ob; bidx[ri] = oi; }
            }
        }
        if (t == 0) {
            const int r0 = wm * 32 + g;
            const int rows[4] = {r0, r0 + 8, r0 + 16, r0 + 24};
            #pragma unroll
            for (int ri = 0; ri < 4; ri++) {
                sh_b[wn * M_TILE + rows[ri]] = best[ri];
                sh_s[wn * M_TILE + rows[ri]] = sec[ri];
                sh_i[wn * M_TILE + rows[ri]] = bidx[ri];
            }
        }
        __syncthreads();

        // ---- outputs: all 256 threads, half-row each ----
        {
            const int r = tid >> 1, h = tid & 1;
            float b0 = sh_b[r], b1 = sh_b[M_TILE + r];
            float s0 = sh_s[r], s1 = sh_s[M_TILE + r];
            int   i0 = sh_i[r], i1 = sh_i[M_TILE + r];
            bool take = (b1 < b0) || (b1 == b0 && i1 < i0);
            float fb = take ? b1 : b0;
            int   fi = take ? i1 : i0;
            float fs = fminf(take ? b0 : b1, fminf(s0, s1));

            const size_t grow = (size_t)tile * M_TILE + r;
            if (h == 0) {
                if (fs - fb < TAU) {
                    int p = atomicAdd(&g_flag_count, 1);
                    g_flag_rows[p] = (int)grow;
                }
                out[grow] = (float)fi;
            }

            const float4* e4  = (const float4*)(cb + (size_t)fi * VQ_D + h * 32);
            const float4* xr4 = (const float4*)(x + grow * VQ_D + h * 32);
            float4* q4 = (float4*)(out + (size_t)n + grow * VQ_D + h * 32);
            float l0 = 0.f, l1 = 0.f, l2 = 0.f, l3 = 0.f;
            #pragma unroll
            for (int j = 0; j < 8; j++) {
                float4 e = e4[j], xv = xr4[j];
                q4[j] = e;
                float d0 = e.x - xv.x, d1 = e.y - xv.y;
                float d2 = e.z - xv.z, d3 = e.w - xv.w;
                l0 = fmaf(d0, d0, l0); l1 = fmaf(d1, d1, l1);
                l2 = fmaf(d2, d2, l2); l3 = fmaf(d3, d3, l3);
            }
            float part = __fadd_rn(__fadd_rn(l0, l1), __fadd_rn(l2, l3));
            part += __shfl_xor_sync(0xffffffffu, part, 1);
            if (h == 0) g_loss_row[grow] = part;
        }
        // top-of-loop wait+sync guards stage/A/sh reuse
    }
}

// ---------------------------------------------------------------------------
// Kernel 2: exact fp32 fixup of flagged rows (bit-identical to the R8 kernel
// arithmetic that passed with zero argmin flips)
// ---------------------------------------------------------------------------
__global__ void __launch_bounds__(256, 1)
vq_fixup_kernel(const float* __restrict__ x,
                const float* __restrict__ cb,
                float* __restrict__ out,
                int n)
{
    if (*(volatile int*)&g_flag_count == 0) return;

    extern __shared__ float sh[];
    float* sh_cb = sh;                 // 512*64
    float* sh_ee = sh + KCODES * VQ_D; // 512

    const int tid = threadIdx.x;
    {
        const float4* cb4 = (const float4*)cb;
        float4* sh4 = (float4*)sh_cb;
        for (int i = tid; i < KCODES * VQ_D / 4; i += 256) sh4[i] = cb4[i];
    }
    __syncthreads();
    for (int kk = tid; kk < KCODES; kk += 256) {
        const float* e = sh_cb + (size_t)kk * VQ_D;
        float a0 = 0.f, a1 = 0.f, a2 = 0.f, a3 = 0.f;
        #pragma unroll
        for (int j = 0; j < VQ_D; j += 4) {
            a0 = fmaf(e[j+0], e[j+0], a0);
            a1 = fmaf(e[j+1], e[j+1], a1);
            a2 = fmaf(e[j+2], e[j+2], a2);
            a3 = fmaf(e[j+3], e[j+3], a3);
        }
        sh_ee[kk] = __fadd_rn(__fadd_rn(a0, a1), __fadd_rn(a2, a3));
    }
    __syncthreads();

    const int count = g_flag_count;
    for (int i = blockIdx.x * 256 + tid; i < count; i += gridDim.x * 256) {
        const int row = g_flag_rows[i];

        u64 xr[VQ_D / 2];
        const ulonglong2* xp = (const ulonglong2*)(x + (size_t)row * VQ_D);
        #pragma unroll
        for (int j = 0; j < VQ_D / 4; j++) {
            ulonglong2 v = xp[j];
            xr[2*j] = v.x; xr[2*j+1] = v.y;
        }
        float xx;
        {
            float a0 = 0.f, a1 = 0.f, a2 = 0.f, a3 = 0.f;
            #pragma unroll
            for (int j = 0; j < VQ_D / 2; j += 2) {
                float2 fa = u2f(xr[j]), fb = u2f(xr[j+1]);
                a0 = fmaf(fa.x, fa.x, a0); a1 = fmaf(fa.y, fa.y, a1);
                a2 = fmaf(fb.x, fb.x, a2); a3 = fmaf(fb.y, fb.y, a3);
            }
            xx = __fadd_rn(__fadd_rn(a0, a1), __fadd_rn(a2, a3));
        }

        float best = 3.402823466e38f;
        int   bi   = 0;
        const ulonglong2* ebase = (const ulonglong2*)sh_cb;
        #pragma unroll 2
        for (int kk = 0; kk < KCODES; kk++) {
            const ulonglong2* e = ebase + (size_t)kk * (VQ_D / 4);
            u64 a0 = 0ull, a1 = 0ull, a2 = 0ull, a3 = 0ull;
            #pragma unroll
            for (int j = 0; j < VQ_D / 4; j += 2) {
                ulonglong2 e0 = e[j];
                ulonglong2 e1 = e[j + 1];
                a0 = fma2(e0.x, xr[2*j    ], a0);
                a1 = fma2(e0.y, xr[2*j + 1], a1);
                a2 = fma2(e1.x, xr[2*j + 2], a2);
                a3 = fma2(e1.y, xr[2*j + 3], a3);
            }
            u64 s = add2(add2(a0, a1), add2(a2, a3));
            float2 sf = u2f(s);
            float dot  = __fadd_rn(sf.x, sf.y);
            float dist = __fadd_rn(__fadd_rn(xx, sh_ee[kk]),
                                   -__fmul_rn(2.0f, dot));
            if (dist < best) { best = dist; bi = kk; }
        }

        out[row] = (float)bi;
        const float*  e  = sh_cb + (size_t)bi * VQ_D;
        const float4* e4 = (const float4*)e;
        float4* q4 = (float4*)(out + (size_t)n + (size_t)row * VQ_D);
        #pragma unroll
        for (int j = 0; j < VQ_D / 4; j++) q4[j] = e4[j];

        float l0 = 0.f, l1 = 0.f, l2 = 0.f, l3 = 0.f;
        #pragma unroll
        for (int j2 = 0; j2 < VQ_D / 2; j2 += 2) {
            float2 fa = u2f(xr[j2]), fb = u2f(xr[j2 + 1]);
            float d0 = e[2*j2 + 0] - fa.x;
            float d1 = e[2*j2 + 1] - fa.y;
            float d2 = e[2*j2 + 2] - fb.x;
            float d3 = e[2*j2 + 3] - fb.y;
            l0 = fmaf(d0, d0, l0); l1 = fmaf(d1, d1, l1);
            l2 = fmaf(d2, d2, l2); l3 = fmaf(d3, d3, l3);
        }
        g_loss_row[row] = __fadd_rn(__fadd_rn(l0, l1), __fadd_rn(l2, l3));
    }
}

// ---------------------------------------------------------------------------
// Kernels 3+4: deterministic staged loss reduction
// ---------------------------------------------------------------------------
__global__ void vq_reduceA_kernel(int n)
{
    __shared__ double shd[256];
    const int base = blockIdx.x * 2048;
    double s = 0.0;
    #pragma unroll
    for (int j = 0; j < 8; j++) {
        int idx = base + j * 256 + threadIdx.x;
        s += (idx < n) ? (double)g_loss_row[idx] : 0.0;
    }
    shd[threadIdx.x] = s;
    __syncthreads();
    for (int off = 128; off > 0; off >>= 1) {
        if (threadIdx.x < off) shd[threadIdx.x] += shd[threadIdx.x + off];
        __syncthreads();
    }
    if (threadIdx.x == 0) g_partials[blockIdx.x] = shd[0];
}

__global__ void vq_reduceB_kernel(float* __restrict__ out, int n)
{
    __shared__ double shd[256];
    shd[threadIdx.x] = g_partials[threadIdx.x];
    __syncthreads();
    for (int off = 128; off > 0; off >>= 1) {
        if (threadIdx.x < off) shd[threadIdx.x] += shd[threadIdx.x + off];
        __syncthreads();
    }
    if (threadIdx.x == 0) {
        double mean = shd[0] / ((double)n * (double)VQ_D);
        out[(size_t)n + (size_t)n * VQ_D] = (float)(mean * 1.25);
    }
}

// ---------------------------------------------------------------------------
extern "C" void kernel_launch(void* const* d_in, const int* in_sizes, int n_in,
                              void* d_out, int out_size)
{
    const float* x  = (const float*)d_in[0];
    const float* cb = (const float*)d_in[1];
    float* out = (float*)d_out;

    const int n = in_sizes[0] / VQ_D;      // 524288
    const int ntiles = n / M_TILE;         // 4096
    int grid = ntiles < 148 ? ntiles : 148;

    static int attr_done = 0;
    if (!attr_done) {
        cudaFuncSetAttribute(vq_main_kernel,
                             cudaFuncAttributeMaxDynamicSharedMemorySize, SM_TOTAL);
        cudaFuncSetAttribute(vq_fixup_kernel,
                             cudaFuncAttributeMaxDynamicSharedMemorySize,
                             (KCODES * VQ_D + KCODES) * 4);
        attr_done = 1;
    }

    vq_init_kernel<<<1, 1>>>();
    vq_main_kernel<<<grid, NTHREADS, SM_TOTAL>>>(x, cb, out, n);
    vq_fixup_kernel<<<64, 256, (KCODES * VQ_D + KCODES) * 4>>>(x, cb, out, n);
    vq_reduceA_kernel<<<256, 256>>>(n);
    vq_reduceB_kernel<<<1, 256>>>(out, n);
}

// round 15
// speedup vs baseline: 1.2024x; 1.2024x over previous
#include <cuda_runtime.h>
#include <cuda_fp16.h>
#include <float.h>

#define VQ_D      64
#define KCODES    512
#define M_TILE    128
#define NTHREADS  512
#define NROWS_MAX 524288
#define TAU       1e-3f

typedef unsigned int       u32;
typedef unsigned long long u64;

// ---------------- global scratch (static: no allocation) ----------------
__device__ int    g_flag_count;
__device__ int    g_flag_rows[NROWS_MAX];
__device__ float  g_loss_row[NROWS_MAX];
__device__ double g_partials[256];

// ---------------- smem layout of main kernel (bytes) ----------------
#define SM_BHI   0                        // 512*128 = 65536  B hi fp16, SW128
#define SM_BLO   (SM_BHI + KCODES*128)    // 65536
#define SM_AHI   (SM_BLO + KCODES*128)    // 131072  128*128
#define SM_ALO   (SM_AHI + M_TILE*128)    // 147456
#define SM_EE    (SM_ALO + M_TILE*128)    // 163840  512 f32
#define SM_SB    (SM_EE  + KCODES*4)      // 165888  2*128 f32 best
#define SM_SS    (SM_SB  + 2*M_TILE*4)    // 166912  2*128 f32 second
#define SM_SI    (SM_SS  + 2*M_TILE*4)    // 167936  2*128 i32 idx
#define SM_TOTAL (SM_SI  + 2*M_TILE*4 + 64)   // ~169 KB

// ---------------- helpers ----------------
__device__ __forceinline__ u32 smem_u32_base(const void* p) {
    u32 a;
    asm("{ .reg .u64 t; cvta.to.shared.u64 t, %1; cvt.u32.u64 %0, t; }"
        : "=r"(a) : "l"(p));
    return a;
}
// swizzled byte offset for 128B-row tiles (SW128: bits[6:4] ^= bits[9:7])
__device__ __forceinline__ u32 swofs(u32 row, u32 off) {
    u32 b = row * 128u + off;
    return b ^ ((b >> 3) & 0x70u);
}
__device__ __forceinline__ void ldsm_x4(u32& r0, u32& r1, u32& r2, u32& r3, u32 addr) {
    asm volatile("ldmatrix.sync.aligned.m8n8.x4.shared.b16 {%0,%1,%2,%3}, [%4];"
        : "=r"(r0), "=r"(r1), "=r"(r2), "=r"(r3) : "r"(addr));
}
__device__ __forceinline__ void mma16816(float* c, const u32* a, u32 b0, u32 b1) {
    asm volatile("mma.sync.aligned.m16n8k16.row.col.f32.f16.f16.f32 "
        "{%0,%1,%2,%3}, {%4,%5,%6,%7}, {%8,%9}, {%0,%1,%2,%3};"
        : "+f"(c[0]), "+f"(c[1]), "+f"(c[2]), "+f"(c[3])
        : "r"(a[0]), "r"(a[1]), "r"(a[2]), "r"(a[3]), "r"(b0), "r"(b1));
}
// fp16 Dekker split: v = (float)hi + (float)lo + O(2^-22 |v|)
__device__ __forceinline__ void split16(float v, __half& hi, __half& lo) {
    hi = __float2half_rn(v);
    lo = __float2half_rn(v - __half2float(hi));
}
// packed f32x2 (exact replica of the R8 arithmetic for the fixup path)
__device__ __forceinline__ u64 fma2(u64 a, u64 b, u64 c) {
    u64 d;
    asm("fma.rn.f32x2 %0, %1, %2, %3;" : "=l"(d) : "l"(a), "l"(b), "l"(c));
    return d;
}
__device__ __forceinline__ u64 add2(u64 a, u64 b) {
    u64 d;
    asm("add.rn.f32x2 %0, %1, %2;" : "=l"(d) : "l"(a), "l"(b));
    return d;
}
__device__ __forceinline__ float2 u2f(u64 a) {
    float2 r;
    r.x = __uint_as_float((unsigned int)(a & 0xffffffffull));
    r.y = __uint_as_float((unsigned int)(a >> 32));
    return r;
}

// ---------------------------------------------------------------------------
__global__ void vq_init_kernel() { g_flag_count = 0; }

// ---------------------------------------------------------------------------
// Kernel 1: tensor-core score pass (fp16 split, 3 terms), 512 threads.
// Score = ||e||^2 - 2<x,e>  (xx dropped: argmin-invariant; near-ties vs the
// reference's rounded distance are caught by the margin flag + exact fixup).
// Warp layout: 16 warps; wm = w&7 -> rows wm*16..+16; wn = w>>3 -> codes
// wn*256..+256. Per thread: 2 rows (g, g+8 within the 16-row group).
// ---------------------------------------------------------------------------
__global__ void __launch_bounds__(NTHREADS, 1)
vq_main_kernel(const float* __restrict__ x,
               const float* __restrict__ cb,
               float* __restrict__ out,
               int n)
{
    extern __shared__ char sm[];
    const u32 su  = smem_u32_base(sm);
    const int tid = threadIdx.x;
    const int w   = tid >> 5;
    const int lid = tid & 31;
    const int wm  = w & 7;        // M group: rows wm*16..+16
    const int wn  = w >> 3;       // N half:  codes wn*256..+256

    float* sh_ee = (float*)(sm + SM_EE);
    float* sh_b  = (float*)(sm + SM_SB);
    float* sh_s  = (float*)(sm + SM_SS);
    int*   sh_i  = (int*)  (sm + SM_SI);

    // ---- codebook: split into B_hi/B_lo fp16 (SW128) + fp32 ||e||^2 ----
    for (int kk = tid; kk < KCODES; kk += NTHREADS) {
        const float4* e4 = (const float4*)(cb + (size_t)kk * VQ_D);
        float a0 = 0.f, a1 = 0.f, a2 = 0.f, a3 = 0.f;
        #pragma unroll
        for (int j = 0; j < 16; j++) {
            float4 v = e4[j];
            __half h0, h1, h2, h3, l0h, l1h, l2h, l3h;
            split16(v.x, h0, l0h); split16(v.y, h1, l1h);
            split16(v.z, h2, l2h); split16(v.w, h3, l3h);
            u32 b = swofs((u32)kk, (u32)j * 8u);
            *(__half2*)(sm + SM_BHI + b)     = __halves2half2(h0, h1);
            *(__half2*)(sm + SM_BHI + b + 4) = __halves2half2(h2, h3);
            *(__half2*)(sm + SM_BLO + b)     = __halves2half2(l0h, l1h);
            *(__half2*)(sm + SM_BLO + b + 4) = __halves2half2(l2h, l3h);
            a0 = fmaf(v.x, v.x, a0); a1 = fmaf(v.y, v.y, a1);
            a2 = fmaf(v.z, v.z, a2); a3 = fmaf(v.w, v.w, a3);
        }
        sh_ee[kk] = __fadd_rn(__fadd_rn(a0, a1), __fadd_rn(a2, a3));
    }

    // per-lane ldmatrix address components
    const u32 arow = (u32)(lid & 7) + ((u32)(lid >> 3) & 1u) * 8u;
    const u32 aoff = ((u32)(lid >> 4) & 1u) * 16u;
    const u32 brow = (u32)(lid & 7) + ((u32)(lid >> 4) & 1u) * 8u;
    const u32 boff = ((u32)(lid >> 3) & 1u) * 16u;
    const int g = lid >> 2, t = lid & 3;

    // x load/convert mapping: thread -> row tid/4, quarter tid&3 (16 floats)
    const int pr = tid >> 2, pq = tid & 3;

    const int ntiles = n / M_TILE;

    for (int tile = blockIdx.x; tile < ntiles; tile += gridDim.x) {
        __syncthreads();   // prev-tile smem readers done before overwrite

        // ---- load + split x tile directly from gmem ----
        {
            const float4* xp = (const float4*)(x + ((size_t)tile * M_TILE + pr) * VQ_D + pq * 16);
            #pragma unroll
            for (int j = 0; j < 4; j++) {
                float4 v = xp[j];
                __half h0, h1, h2, h3, l0h, l1h, l2h, l3h;
                split16(v.x, h0, l0h); split16(v.y, h1, l1h);
                split16(v.z, h2, l2h); split16(v.w, h3, l3h);
                u32 b = swofs((u32)pr, (u32)(pq * 32 + j * 8));
                *(__half2*)(sm + SM_AHI + b)     = __halves2half2(h0, h1);
                *(__half2*)(sm + SM_AHI + b + 4) = __halves2half2(h2, h3);
                *(__half2*)(sm + SM_ALO + b)     = __halves2half2(l0h, l1h);
                *(__half2*)(sm + SM_ALO + b + 4) = __halves2half2(l2h, l3h);
            }
        }
        __syncthreads();   // A ready

        // ---- A fragments: this warp's 16 rows (hi & lo), all 4 k-chunks ----
        u32 ahi[4][4], alo[4][4];
        #pragma unroll
        for (int k = 0; k < 4; k++) {
            u32 o = swofs((u32)(wm * 16) + arow, (u32)k * 32u + aoff);
            ldsm_x4(ahi[k][0], ahi[k][1], ahi[k][2], ahi[k][3], su + SM_AHI + o);
            ldsm_x4(alo[k][0], alo[k][1], alo[k][2], alo[k][3], su + SM_ALO + o);
        }

        float best[2] = {FLT_MAX, FLT_MAX};
        float sec [2] = {FLT_MAX, FLT_MAX};
        int   bidx[2] = {0, 0};

        #pragma unroll 1
        for (int chunk = 0; chunk < 4; chunk++) {
            const int nbase = wn * 256 + chunk * 64;
            float acc[8][4];
            #pragma unroll
            for (int j = 0; j < 8; j++)
                #pragma unroll
                for (int q = 0; q < 4; q++) acc[j][q] = 0.f;

            #pragma unroll
            for (int k = 0; k < 4; k++) {
                u32 bh0[8], bh1[8], bl0[8], bl1[8];
                #pragma unroll
                for (int gi = 0; gi < 4; gi++) {
                    u32 o = swofs((u32)(nbase + gi * 16) + brow, (u32)k * 32u + boff);
                    ldsm_x4(bh0[2*gi], bh1[2*gi], bh0[2*gi+1], bh1[2*gi+1], su + SM_BHI + o);
                    ldsm_x4(bl0[2*gi], bl1[2*gi], bl0[2*gi+1], bl1[2*gi+1], su + SM_BLO + o);
                }
                #pragma unroll
                for (int j = 0; j < 8; j++) {
                    mma16816(acc[j], ahi[k], bh0[j], bh1[j]);  // hi*hi
                    mma16816(acc[j], alo[k], bh0[j], bh1[j]);  // lo*hi
                    mma16816(acc[j], ahi[k], bl0[j], bl1[j]);  // hi*lo
                }
            }

            // ---- epilogue: score = ee - 2*dot, top-2 tracking (2 rows) ----
            #pragma unroll
            for (int j = 0; j < 8; j++) {
                const int c0 = nbase + j * 8 + 2 * t;
                float2 ee = *(const float2*)(&sh_ee[c0]);
                float d00 = fmaf(acc[j][0], -2.f, ee.x);
                float d01 = fmaf(acc[j][1], -2.f, ee.y);
                float d10 = fmaf(acc[j][2], -2.f, ee.x);
                float d11 = fmaf(acc[j][3], -2.f, ee.y);
                #define UPD(r_, d_, c_) \
                    if ((d_) < best[r_]) { sec[r_] = best[r_]; best[r_] = (d_); bidx[r_] = (c_); } \
                    else sec[r_] = fminf(sec[r_], (d_));
                UPD(0, d00, c0); UPD(0, d01, c0 + 1);
                UPD(1, d10, c0); UPD(1, d11, c0 + 1);
                #undef UPD
            }
        }

        // ---- intra-warp merge over the 4 t-lanes sharing each row ----
        #pragma unroll
        for (int off = 1; off <= 2; off <<= 1) {
            #pragma unroll
            for (int ri = 0; ri < 2; ri++) {
                float ob = __shfl_xor_sync(0xffffffffu, best[ri], off);
                float os = __shfl_xor_sync(0xffffffffu, sec[ri],  off);
                int   oi = __shfl_xor_sync(0xffffffffu, bidx[ri], off);
                bool take = (ob < best[ri]) || (ob == best[ri] && oi < bidx[ri]);
                float loser = take ? best[ri] : ob;
                sec[ri] = fminf(loser, fminf(sec[ri], os));
                if (take) { best[ri] = ob; bidx[ri] = oi; }
            }
        }
        if (t == 0) {
            const int r0 = wm * 16 + g;
            #pragma unroll
            for (int ri = 0; ri < 2; ri++) {
                const int r = r0 + ri * 8;
                sh_b[wn * M_TILE + r] = best[ri];
                sh_s[wn * M_TILE + r] = sec[ri];
                sh_i[wn * M_TILE + r] = bidx[ri];
            }
        }
        __syncthreads();

        // ---- outputs: 512 threads, quarter-row each ----
        {
            const int r = pr, h = pq;
            float b0 = sh_b[r], b1 = sh_b[M_TILE + r];
            float s0 = sh_s[r], s1 = sh_s[M_TILE + r];
            int   i0 = sh_i[r], i1 = sh_i[M_TILE + r];
            bool take = (b1 < b0) || (b1 == b0 && i1 < i0);
            float fb = take ? b1 : b0;
            int   fi = take ? i1 : i0;
            float fs = fminf(take ? b0 : b1, fminf(s0, s1));

            const size_t grow = (size_t)tile * M_TILE + r;
            if (h == 0) {
                if (fs - fb < TAU) {
                    int p = atomicAdd(&g_flag_count, 1);
                    g_flag_rows[p] = (int)grow;
                }
                out[grow] = (float)fi;
            }

            const float4* e4  = (const float4*)(cb + (size_t)fi * VQ_D + h * 16);
            const float4* xr4 = (const float4*)(x + grow * VQ_D + h * 16);
            float4* q4 = (float4*)(out + (size_t)n + grow * VQ_D + h * 16);
            float l0 = 0.f, l1 = 0.f, l2 = 0.f, l3 = 0.f;
            #pragma unroll
            for (int j = 0; j < 4; j++) {
                float4 e = e4[j], xv = xr4[j];
                q4[j] = e;
                float d0 = e.x - xv.x, d1 = e.y - xv.y;
                float d2 = e.z - xv.z, d3 = e.w - xv.w;
                l0 = fmaf(d0, d0, l0); l1 = fmaf(d1, d1, l1);
                l2 = fmaf(d2, d2, l2); l3 = fmaf(d3, d3, l3);
            }
            float part = __fadd_rn(__fadd_rn(l0, l1), __fadd_rn(l2, l3));
            part += __shfl_xor_sync(0xffffffffu, part, 1);
            part += __shfl_xor_sync(0xffffffffu, part, 2);
            if (h == 0) g_loss_row[grow] = part;
        }
        // top-of-loop sync guards smem reuse
    }
}

// ---------------------------------------------------------------------------
// Kernel 2: exact fp32 fixup of flagged rows (bit-identical to the R8 kernel
// arithmetic that passed with zero argmin flips)
// ---------------------------------------------------------------------------
__global__ void __launch_bounds__(256, 1)
vq_fixup_kernel(const float* __restrict__ x,
                const float* __restrict__ cb,
                float* __restrict__ out,
                int n)
{
    if (*(volatile int*)&g_flag_count == 0) return;

    extern __shared__ float sh[];
    float* sh_cb = sh;                 // 512*64
    float* sh_ee = sh + KCODES * VQ_D; // 512

    const int tid = threadIdx.x;
    {
        const float4* cb4 = (const float4*)cb;
        float4* sh4 = (float4*)sh_cb;
        for (int i = tid; i < KCODES * VQ_D / 4; i += 256) sh4[i] = cb4[i];
    }
    __syncthreads();
    for (int kk = tid; kk < KCODES; kk += 256) {
        const float* e = sh_cb + (size_t)kk * VQ_D;
        float a0 = 0.f, a1 = 0.f, a2 = 0.f, a3 = 0.f;
        #pragma unroll
        for (int j = 0; j < VQ_D; j += 4) {
            a0 = fmaf(e[j+0], e[j+0], a0);
            a1 = fmaf(e[j+1], e[j+1], a1);
            a2 = fmaf(e[j+2], e[j+2], a2);
            a3 = fmaf(e[j+3], e[j+3], a3);
        }
        sh_ee[kk] = __fadd_rn(__fadd_rn(a0, a1), __fadd_rn(a2, a3));
    }
    __syncthreads();

    const int count = g_flag_count;
    for (int i = blockIdx.x * 256 + tid; i < count; i += gridDim.x * 256) {
        const int row = g_flag_rows[i];

        u64 xr[VQ_D / 2];
        const ulonglong2* xp = (const ulonglong2*)(x + (size_t)row * VQ_D);
        #pragma unroll
        for (int j = 0; j < VQ_D / 4; j++) {
            ulonglong2 v = xp[j];
            xr[2*j] = v.x; xr[2*j+1] = v.y;
        }
        float xx;
        {
            float a0 = 0.f, a1 = 0.f, a2 = 0.f, a3 = 0.f;
            #pragma unroll
            for (int j = 0; j < VQ_D / 2; j += 2) {
                float2 fa = u2f(xr[j]), fb = u2f(xr[j+1]);
                a0 = fmaf(fa.x, fa.x, a0); a1 = fmaf(fa.y, fa.y, a1);
                a2 = fmaf(fb.x, fb.x, a2); a3 = fmaf(fb.y, fb.y, a3);
            }
            xx = __fadd_rn(__fadd_rn(a0, a1), __fadd_rn(a2, a3));
        }

        float best = 3.402823466e38f;
        int   bi   = 0;
        const ulonglong2* ebase = (const ulonglong2*)sh_cb;
        #pragma unroll 2
        for (int kk = 0; kk < KCODES; kk++) {
            const ulonglong2* e = ebase + (size_t)kk * (VQ_D / 4);
            u64 a0 = 0ull, a1 = 0ull, a2 = 0ull, a3 = 0ull;
            #pragma unroll
            for (int j = 0; j < VQ_D / 4; j += 2) {
                ulonglong2 e0 = e[j];
                ulonglong2 e1 = e[j + 1];
                a0 = fma2(e0.x, xr[2*j    ], a0);
                a1 = fma2(e0.y, xr[2*j + 1], a1);
                a2 = fma2(e1.x, xr[2*j + 2], a2);
                a3 = fma2(e1.y, xr[2*j + 3], a3);
            }
            u64 s = add2(add2(a0, a1), add2(a2, a3));
            float2 sf = u2f(s);
            float dot  = __fadd_rn(sf.x, sf.y);
            float dist = __fadd_rn(__fadd_rn(xx, sh_ee[kk]),
                                   -__fmul_rn(2.0f, dot));
            if (dist < best) { best = dist; bi = kk; }
        }

        out[row] = (float)bi;
        const float*  e  = sh_cb + (size_t)bi * VQ_D;
        const float4* e4 = (const float4*)e;
        float4* q4 = (float4*)(out + (size_t)n + (size_t)row * VQ_D);
        #pragma unroll
        for (int j = 0; j < VQ_D / 4; j++) q4[j] = e4[j];

        float l0 = 0.f, l1 = 0.f, l2 = 0.f, l3 = 0.f;
        #pragma unroll
        for (int j2 = 0; j2 < VQ_D / 2; j2 += 2) {
            float2 fa = u2f(xr[j2]), fb = u2f(xr[j2 + 1]);
            float d0 = e[2*j2 + 0] - fa.x;
            float d1 = e[2*j2 + 1] - fa.y;
            float d2 = e[2*j2 + 2] - fb.x;
            float d3 = e[2*j2 + 3] - fb.y;
            l0 = fmaf(d0, d0, l0); l1 = fmaf(d1, d1, l1);
            l2 = fmaf(d2, d2, l2); l3 = fmaf(d3, d3, l3);
        }
        g_loss_row[row] = __fadd_rn(__fadd_rn(l0, l1), __fadd_rn(l2, l3));
    }
}

// ---------------------------------------------------------------------------
// Kernels 3+4: deterministic staged loss reduction
// ---------------------------------------------------------------------------
__global__ void vq_reduceA_kernel(int n)
{
    __shared__ double shd[256];
    const int base = blockIdx.x * 2048;
    double s = 0.0;
    #pragma unroll
    for (int j = 0; j < 8; j++) {
        int idx = base + j * 256 + threadIdx.x;
        s += (idx < n) ? (double)g_loss_row[idx] : 0.0;
    }
    shd[threadIdx.x] = s;
    __syncthreads();
    for (int off = 128; off > 0; off >>= 1) {
        if (threadIdx.x < off) shd[threadIdx.x] += shd[threadIdx.x + off];
        __syncthreads();
    }
    if (threadIdx.x == 0) g_partials[blockIdx.x] = shd[0];
}

__global__ void vq_reduceB_kernel(float* __restrict__ out, int n)
{
    __shared__ double shd[256];
    shd[threadIdx.x] = g_partials[threadIdx.x];
    __syncthreads();
    for (int off = 128; off > 0; off >>= 1) {
        if (threadIdx.x < off) shd[threadIdx.x] += shd[threadIdx.x + off];
        __syncthreads();
    }
    if (threadIdx.x == 0) {
        double mean = shd[0] / ((double)n * (double)VQ_D);
        out[(size_t)n + (size_t)n * VQ_D] = (float)(mean * 1.25);
    }
}

// ---------------------------------------------------------------------------
extern "C" void kernel_launch(void* const* d_in, const int* in_sizes, int n_in,
                              void* d_out, int out_size)
{
    const float* x  = (const float*)d_in[0];
    const float* cb = (const float*)d_in[1];
    float* out = (float*)d_out;

    const int n = in_sizes[0] / VQ_D;      // 524288
    const int ntiles = n / M_TILE;         // 4096
    int grid = ntiles < 148 ? ntiles : 148;

    static int attr_done = 0;
    if (!attr_done) {
        cudaFuncSetAttribute(vq_main_kernel,
                             cudaFuncAttributeMaxDynamicSharedMemorySize, SM_TOTAL);
        cudaFuncSetAttribute(vq_fixup_kernel,
                             cudaFuncAttributeMaxDynamicSharedMemorySize,
                             (KCODES * VQ_D + KCODES) * 4);
        attr_done = 1;
    }

    vq_init_kernel<<<1, 1>>>();
    vq_main_kernel<<<grid, NTHREADS, SM_TOTAL>>>(x, cb, out, n);
    vq_fixup_kernel<<<64, 256, (KCODES * VQ_D + KCODES) * 4>>>(x, cb, out, n);
    vq_reduceA_kernel<<<256, 256>>>(n);
    vq_reduceB_kernel<<<1, 256>>>(out, n);
}

// round 16
// speedup vs baseline: 1.2473x; 1.0374x over previous
#include <cuda_runtime.h>
#include <cuda_fp16.h>
#include <float.h>

#define VQ_D      64
#define KCODES    512
#define M_TILE    128
#define NTHREADS  512
#define NROWS_MAX 524288
#define TAU       2e-2f

typedef unsigned int       u32;
typedef unsigned long long u64;

// ---------------- global scratch (static: no allocation) ----------------
__device__ int    g_flag_count;
__device__ int    g_flag_rows[NROWS_MAX];
__device__ float  g_loss_row[NROWS_MAX];
__device__ double g_partials[256];

// ---------------- smem layout of main kernel (bytes) ----------------
#define SM_BHI   0                        // 512*128 = 65536  B hi fp16, SW128
#define SM_AHI   (SM_BHI + KCODES*128)    // 65536   128*128  A hi
#define SM_ALO   (SM_AHI + M_TILE*128)    // 81920   128*128  A lo
#define SM_EE    (SM_ALO + M_TILE*128)    // 98304   512 f32
#define SM_SB    (SM_EE  + KCODES*4)      // 100352  2*128 f32 best
#define SM_SS    (SM_SB  + 2*M_TILE*4)    // 101376  2*128 f32 second
#define SM_SI    (SM_SS  + 2*M_TILE*4)    // 102400  2*128 i32 idx
#define SM_TOTAL (SM_SI  + 2*M_TILE*4 + 64)   // ~104 KB

// ---------------- helpers ----------------
__device__ __forceinline__ u32 smem_u32_base(const void* p) {
    u32 a;
    asm("{ .reg .u64 t; cvta.to.shared.u64 t, %1; cvt.u32.u64 %0, t; }"
        : "=r"(a) : "l"(p));
    return a;
}
// swizzled byte offset for 128B-row tiles (SW128: bits[6:4] ^= bits[9:7])
__device__ __forceinline__ u32 swofs(u32 row, u32 off) {
    u32 b = row * 128u + off;
    return b ^ ((b >> 3) & 0x70u);
}
__device__ __forceinline__ void ldsm_x4(u32& r0, u32& r1, u32& r2, u32& r3, u32 addr) {
    asm volatile("ldmatrix.sync.aligned.m8n8.x4.shared.b16 {%0,%1,%2,%3}, [%4];"
        : "=r"(r0), "=r"(r1), "=r"(r2), "=r"(r3) : "r"(addr));
}
__device__ __forceinline__ void mma16816(float* c, const u32* a, u32 b0, u32 b1) {
    asm volatile("mma.sync.aligned.m16n8k16.row.col.f32.f16.f16.f32 "
        "{%0,%1,%2,%3}, {%4,%5,%6,%7}, {%8,%9}, {%0,%1,%2,%3};"
        : "+f"(c[0]), "+f"(c[1]), "+f"(c[2]), "+f"(c[3])
        : "r"(a[0]), "r"(a[1]), "r"(a[2]), "r"(a[3]), "r"(b0), "r"(b1));
}
// fp16 Dekker split: v = (float)hi + (float)lo + O(2^-22 |v|)
__device__ __forceinline__ void split16(float v, __half& hi, __half& lo) {
    hi = __float2half_rn(v);
    lo = __float2half_rn(v - __half2float(hi));
}
// packed f32x2 (exact replica of the R8 arithmetic for the fixup path)
__device__ __forceinline__ u64 fma2(u64 a, u64 b, u64 c) {
    u64 d;
    asm("fma.rn.f32x2 %0, %1, %2, %3;" : "=l"(d) : "l"(a), "l"(b), "l"(c));
    return d;
}
__device__ __forceinline__ u64 add2(u64 a, u64 b) {
    u64 d;
    asm("add.rn.f32x2 %0, %1, %2;" : "=l"(d) : "l"(a), "l"(b));
    return d;
}
__device__ __forceinline__ float2 u2f(u64 a) {
    float2 r;
    r.x = __uint_as_float((unsigned int)(a & 0xffffffffull));
    r.y = __uint_as_float((unsigned int)(a >> 32));
    return r;
}

// ---------------------------------------------------------------------------
__global__ void vq_init_kernel() { g_flag_count = 0; }

// ---------------------------------------------------------------------------
// Kernel 1: tensor-core score pass, 512 threads, 2-term fp16 split:
//   dot = (a_hi + a_lo) . b_hi  =  x . b_hi   (exact up to fp32 accum)
//   score = ||e||^2 - 2*dot ;  error vs exact score = 2*x.b_lo (std ~2.7e-3)
// Rows whose top-2 margin < TAU=2e-2 (~7.4 sigma) go to the exact fixup.
// Warp layout: 16 warps; wm = w&7 -> rows wm*16..+16; wn = w>>3 -> codes
// wn*256..+256. Per thread: 2 rows (g, g+8 within the 16-row group).
// ---------------------------------------------------------------------------
__global__ void __launch_bounds__(NTHREADS, 1)
vq_main_kernel(const float* __restrict__ x,
               const float* __restrict__ cb,
               float* __restrict__ out,
               int n)
{
    extern __shared__ char sm[];
    const u32 su  = smem_u32_base(sm);
    const int tid = threadIdx.x;
    const int w   = tid >> 5;
    const int lid = tid & 31;
    const int wm  = w & 7;        // M group: rows wm*16..+16
    const int wn  = w >> 3;       // N half:  codes wn*256..+256

    float* sh_ee = (float*)(sm + SM_EE);
    float* sh_b  = (float*)(sm + SM_SB);
    float* sh_s  = (float*)(sm + SM_SS);
    int*   sh_i  = (int*)  (sm + SM_SI);

    // ---- codebook: B_hi fp16 (SW128) + fp32 ||e||^2 ----
    for (int kk = tid; kk < KCODES; kk += NTHREADS) {
        const float4* e4 = (const float4*)(cb + (size_t)kk * VQ_D);
        float a0 = 0.f, a1 = 0.f, a2 = 0.f, a3 = 0.f;
        #pragma unroll
        for (int j = 0; j < 16; j++) {
            float4 v = e4[j];
            u32 b = swofs((u32)kk, (u32)j * 8u);
            *(__half2*)(sm + SM_BHI + b)     = __halves2half2(__float2half_rn(v.x),
                                                              __float2half_rn(v.y));
            *(__half2*)(sm + SM_BHI + b + 4) = __halves2half2(__float2half_rn(v.z),
                                                              __float2half_rn(v.w));
            a0 = fmaf(v.x, v.x, a0); a1 = fmaf(v.y, v.y, a1);
            a2 = fmaf(v.z, v.z, a2); a3 = fmaf(v.w, v.w, a3);
        }
        sh_ee[kk] = __fadd_rn(__fadd_rn(a0, a1), __fadd_rn(a2, a3));
    }

    // per-lane ldmatrix address components
    const u32 arow = (u32)(lid & 7) + ((u32)(lid >> 3) & 1u) * 8u;
    const u32 aoff = ((u32)(lid >> 4) & 1u) * 16u;
    const u32 brow = (u32)(lid & 7) + ((u32)(lid >> 4) & 1u) * 8u;
    const u32 boff = ((u32)(lid >> 3) & 1u) * 16u;
    const int g = lid >> 2, t = lid & 3;

    // x load/convert mapping: thread -> row tid/4, quarter tid&3 (16 floats)
    const int pr = tid >> 2, pq = tid & 3;

    const int ntiles = n / M_TILE;

    for (int tile = blockIdx.x; tile < ntiles; tile += gridDim.x) {
        __syncthreads();   // prev-tile smem readers done before overwrite

        // ---- load + split x tile directly from gmem ----
        {
            const float4* xp = (const float4*)(x + ((size_t)tile * M_TILE + pr) * VQ_D + pq * 16);
            #pragma unroll
            for (int j = 0; j < 4; j++) {
                float4 v = xp[j];
                __half h0, h1, h2, h3, l0h, l1h, l2h, l3h;
                split16(v.x, h0, l0h); split16(v.y, h1, l1h);
                split16(v.z, h2, l2h); split16(v.w, h3, l3h);
                u32 b = swofs((u32)pr, (u32)(pq * 32 + j * 8));
                *(__half2*)(sm + SM_AHI + b)     = __halves2half2(h0, h1);
                *(__half2*)(sm + SM_AHI + b + 4) = __halves2half2(h2, h3);
                *(__half2*)(sm + SM_ALO + b)     = __halves2half2(l0h, l1h);
                *(__half2*)(sm + SM_ALO + b + 4) = __halves2half2(l2h, l3h);
            }
        }
        __syncthreads();   // A ready

        // ---- A fragments: this warp's 16 rows (hi & lo), all 4 k-chunks ----
        u32 ahi[4][4], alo[4][4];
        #pragma unroll
        for (int k = 0; k < 4; k++) {
            u32 o = swofs((u32)(wm * 16) + arow, (u32)k * 32u + aoff);
            ldsm_x4(ahi[k][0], ahi[k][1], ahi[k][2], ahi[k][3], su + SM_AHI + o);
            ldsm_x4(alo[k][0], alo[k][1], alo[k][2], alo[k][3], su + SM_ALO + o);
        }

        float best[2] = {FLT_MAX, FLT_MAX};
        float sec [2] = {FLT_MAX, FLT_MAX};
        int   bidx[2] = {0, 0};

        #pragma unroll 1
        for (int chunk = 0; chunk < 4; chunk++) {
            const int nbase = wn * 256 + chunk * 64;
            float acc[8][4];
            #pragma unroll
            for (int j = 0; j < 8; j++)
                #pragma unroll
                for (int q = 0; q < 4; q++) acc[j][q] = 0.f;

            #pragma unroll
            for (int k = 0; k < 4; k++) {
                u32 bh0[8], bh1[8];
                #pragma unroll
                for (int gi = 0; gi < 4; gi++) {
                    u32 o = swofs((u32)(nbase + gi * 16) + brow, (u32)k * 32u + boff);
                    ldsm_x4(bh0[2*gi], bh1[2*gi], bh0[2*gi+1], bh1[2*gi+1], su + SM_BHI + o);
                }
                #pragma unroll
                for (int j = 0; j < 8; j++) {
                    mma16816(acc[j], ahi[k], bh0[j], bh1[j]);  // hi * b_hi
                    mma16816(acc[j], alo[k], bh0[j], bh1[j]);  // lo * b_hi
                }
            }

            // ---- epilogue: score = ee - 2*dot, top-2 tracking (2 rows) ----
            #pragma unroll
            for (int j = 0; j < 8; j++) {
                const int c0 = nbase + j * 8 + 2 * t;
                float2 ee = *(const float2*)(&sh_ee[c0]);
                float d00 = fmaf(acc[j][0], -2.f, ee.x);
                float d01 = fmaf(acc[j][1], -2.f, ee.y);
                float d10 = fmaf(acc[j][2], -2.f, ee.x);
                float d11 = fmaf(acc[j][3], -2.f, ee.y);
                #define UPD(r_, d_, c_) \
                    if ((d_) < best[r_]) { sec[r_] = best[r_]; best[r_] = (d_); bidx[r_] = (c_); } \
                    else sec[r_] = fminf(sec[r_], (d_));
                UPD(0, d00, c0); UPD(0, d01, c0 + 1);
                UPD(1, d10, c0); UPD(1, d11, c0 + 1);
                #undef UPD
            }
        }

        // ---- intra-warp merge over the 4 t-lanes sharing each row ----
        #pragma unroll
        for (int off = 1; off <= 2; off <<= 1) {
            #pragma unroll
            for (int ri = 0; ri < 2; ri++) {
                float ob = __shfl_xor_sync(0xffffffffu, best[ri], off);
                float os = __shfl_xor_sync(0xffffffffu, sec[ri],  off);
                int   oi = __shfl_xor_sync(0xffffffffu, bidx[ri], off);
                bool take = (ob < best[ri]) || (ob == best[ri] && oi < bidx[ri]);
                float loser = take ? best[ri] : ob;
                sec[ri] = fminf(loser, fminf(sec[ri], os));
                if (take) { best[ri] = ob; bidx[ri] = oi; }
            }
        }
        if (t == 0) {
            const int r0 = wm * 16 + g;
            #pragma unroll
            for (int ri = 0; ri < 2; ri++) {
                const int r = r0 + ri * 8;
                sh_b[wn * M_TILE + r] = best[ri];
                sh_s[wn * M_TILE + r] = sec[ri];
                sh_i[wn * M_TILE + r] = bidx[ri];
            }
        }
        __syncthreads();

        // ---- outputs: 512 threads, quarter-row each ----
        {
            const int r = pr, h = pq;
            float b0 = sh_b[r], b1 = sh_b[M_TILE + r];
            float s0 = sh_s[r], s1 = sh_s[M_TILE + r];
            int   i0 = sh_i[r], i1 = sh_i[M_TILE + r];
            bool take = (b1 < b0) || (b1 == b0 && i1 < i0);
            float fb = take ? b1 : b0;
            int   fi = take ? i1 : i0;
            float fs = fminf(take ? b0 : b1, fminf(s0, s1));

            const size_t grow = (size_t)tile * M_TILE + r;
            if (h == 0) {
                if (fs - fb < TAU) {
                    int p = atomicAdd(&g_flag_count, 1);
                    g_flag_rows[p] = (int)grow;
                }
                out[grow] = (float)fi;
            }

            const float4* e4  = (const float4*)(cb + (size_t)fi * VQ_D + h * 16);
            const float4* xr4 = (const float4*)(x + grow * VQ_D + h * 16);
            float4* q4 = (float4*)(out + (size_t)n + grow * VQ_D + h * 16);
            float l0 = 0.f, l1 = 0.f, l2 = 0.f, l3 = 0.f;
            #pragma unroll
            for (int j = 0; j < 4; j++) {
                float4 e = e4[j], xv = xr4[j];
                q4[j] = e;
                float d0 = e.x - xv.x, d1 = e.y - xv.y;
                float d2 = e.z - xv.z, d3 = e.w - xv.w;
                l0 = fmaf(d0, d0, l0); l1 = fmaf(d1, d1, l1);
                l2 = fmaf(d2, d2, l2); l3 = fmaf(d3, d3, l3);
            }
            float part = __fadd_rn(__fadd_rn(l0, l1), __fadd_rn(l2, l3));
            part += __shfl_xor_sync(0xffffffffu, part, 1);
            part += __shfl_xor_sync(0xffffffffu, part, 2);
            if (h == 0) g_loss_row[grow] = part;
        }
        // top-of-loop sync guards smem reuse
    }
}

// ---------------------------------------------------------------------------
// Kernel 2: exact fp32 fixup of flagged rows (bit-identical to the R8 kernel
// arithmetic that passed with zero argmin flips)
// ---------------------------------------------------------------------------
__global__ void __launch_bounds__(256, 1)
vq_fixup_kernel(const float* __restrict__ x,
                const float* __restrict__ cb,
                float* __restrict__ out,
                int n)
{
    if (*(volatile int*)&g_flag_count == 0) return;

    extern __shared__ float sh[];
    float* sh_cb = sh;                 // 512*64
    float* sh_ee = sh + KCODES * VQ_D; // 512

    const int tid = threadIdx.x;
    {
        const float4* cb4 = (const float4*)cb;
        float4* sh4 = (float4*)sh_cb;
        for (int i = tid; i < KCODES * VQ_D / 4; i += 256) sh4[i] = cb4[i];
    }
    __syncthreads();
    for (int kk = tid; kk < KCODES; kk += 256) {
        const float* e = sh_cb + (size_t)kk * VQ_D;
        float a0 = 0.f, a1 = 0.f, a2 = 0.f, a3 = 0.f;
        #pragma unroll
        for (int j = 0; j < VQ_D; j += 4) {
            a0 = fmaf(e[j+0], e[j+0], a0);
            a1 = fmaf(e[j+1], e[j+1], a1);
            a2 = fmaf(e[j+2], e[j+2], a2);
            a3 = fmaf(e[j+3], e[j+3], a3);
        }
        sh_ee[kk] = __fadd_rn(__fadd_rn(a0, a1), __fadd_rn(a2, a3));
    }
    __syncthreads();

    const int count = g_flag_count;
    for (int i = blockIdx.x * 256 + tid; i < count; i += gridDim.x * 256) {
        const int row = g_flag_rows[i];

        u64 xr[VQ_D / 2];
        const ulonglong2* xp = (const ulonglong2*)(x + (size_t)row * VQ_D);
        #pragma unroll
        for (int j = 0; j < VQ_D / 4; j++) {
            ulonglong2 v = xp[j];
            xr[2*j] = v.x; xr[2*j+1] = v.y;
        }
        float xx;
        {
            float a0 = 0.f, a1 = 0.f, a2 = 0.f, a3 = 0.f;
            #pragma unroll
            for (int j = 0; j < VQ_D / 2; j += 2) {
                float2 fa = u2f(xr[j]), fb = u2f(xr[j+1]);
                a0 = fmaf(fa.x, fa.x, a0); a1 = fmaf(fa.y, fa.y, a1);
                a2 = fmaf(fb.x, fb.x, a2); a3 = fmaf(fb.y, fb.y, a3);
            }
            xx = __fadd_rn(__fadd_rn(a0, a1), __fadd_rn(a2, a3));
        }

        float best = 3.402823466e38f;
        int   bi   = 0;
        const ulonglong2* ebase = (const ulonglong2*)sh_cb;
        #pragma unroll 2
        for (int kk = 0; kk < KCODES; kk++) {
            const ulonglong2* e = ebase + (size_t)kk * (VQ_D / 4);
            u64 a0 = 0ull, a1 = 0ull, a2 = 0ull, a3 = 0ull;
            #pragma unroll
            for (int j = 0; j < VQ_D / 4; j += 2) {
                ulonglong2 e0 = e[j];
                ulonglong2 e1 = e[j + 1];
                a0 = fma2(e0.x, xr[2*j    ], a0);
                a1 = fma2(e0.y, xr[2*j + 1], a1);
                a2 = fma2(e1.x, xr[2*j + 2], a2);
                a3 = fma2(e1.y, xr[2*j + 3], a3);
            }
            u64 s = add2(add2(a0, a1), add2(a2, a3));
            float2 sf = u2f(s);
            float dot  = __fadd_rn(sf.x, sf.y);
            float dist = __fadd_rn(__fadd_rn(xx, sh_ee[kk]),
                                   -__fmul_rn(2.0f, dot));
            if (dist < best) { best = dist; bi = kk; }
        }

        out[row] = (float)bi;
        const float*  e  = sh_cb + (size_t)bi * VQ_D;
        const float4* e4 = (const float4*)e;
        float4* q4 = (float4*)(out + (size_t)n + (size_t)row * VQ_D);
        #pragma unroll
        for (int j = 0; j < VQ_D / 4; j++) q4[j] = e4[j];

        float l0 = 0.f, l1 = 0.f, l2 = 0.f, l3 = 0.f;
        #pragma unroll
        for (int j2 = 0; j2 < VQ_D / 2; j2 += 2) {
            float2 fa = u2f(xr[j2]), fb = u2f(xr[j2 + 1]);
            float d0 = e[2*j2 + 0] - fa.x;
            float d1 = e[2*j2 + 1] - fa.y;
            float d2 = e[2*j2 + 2] - fb.x;
            float d3 = e[2*j2 + 3] - fb.y;
            l0 = fmaf(d0, d0, l0); l1 = fmaf(d1, d1, l1);
            l2 = fmaf(d2, d2, l2); l3 = fmaf(d3, d3, l3);
        }
        g_loss_row[row] = __fadd_rn(__fadd_rn(l0, l1), __fadd_rn(l2, l3));
    }
}

// ---------------------------------------------------------------------------
// Kernels 3+4: deterministic staged loss reduction
// ---------------------------------------------------------------------------
__global__ void vq_reduceA_kernel(int n)
{
    __shared__ double shd[256];
    const int base = blockIdx.x * 2048;
    double s = 0.0;
    #pragma unroll
    for (int j = 0; j < 8; j++) {
        int idx = base + j * 256 + threadIdx.x;
        s += (idx < n) ? (double)g_loss_row[idx] : 0.0;
    }
    shd[threadIdx.x] = s;
    __syncthreads();
    for (int off = 128; off > 0; off >>= 1) {
        if (threadIdx.x < off) shd[threadIdx.x] += shd[threadIdx.x + off];
        __syncthreads();
    }
    if (threadIdx.x == 0) g_partials[blockIdx.x] = shd[0];
}

__global__ void vq_reduceB_kernel(float* __restrict__ out, int n)
{
    __shared__ double shd[256];
    shd[threadIdx.x] = g_partials[threadIdx.x];
    __syncthreads();
    for (int off = 128; off > 0; off >>= 1) {
        if (threadIdx.x < off) shd[threadIdx.x] += shd[threadIdx.x + off];
        __syncthreads();
    }
    if (threadIdx.x == 0) {
        double mean = shd[0] / ((double)n * (double)VQ_D);
        out[(size_t)n + (size_t)n * VQ_D] = (float)(mean * 1.25);
    }
}

// ---------------------------------------------------------------------------
extern "C" void kernel_launch(void* const* d_in, const int* in_sizes, int n_in,
                              void* d_out, int out_size)
{
    const float* x  = (const float*)d_in[0];
    const float* cb = (const float*)d_in[1];
    float* out = (float*)d_out;

    const int n = in_sizes[0] / VQ_D;      // 524288
    const int ntiles = n / M_TILE;         // 4096
    int grid = ntiles < 148 ? ntiles : 148;

    static int attr_done = 0;
    if (!attr_done) {
        cudaFuncSetAttribute(vq_main_kernel,
                             cudaFuncAttributeMaxDynamicSharedMemorySize, SM_TOTAL);
        cudaFuncSetAttribute(vq_fixup_kernel,
                             cudaFuncAttributeMaxDynamicSharedMemorySize,
                             (KCODES * VQ_D + KCODES) * 4);
        attr_done = 1;
    }

    vq_init_kernel<<<1, 1>>>();
    vq_main_kernel<<<grid, NTHREADS, SM_TOTAL>>>(x, cb, out, n);
    vq_fixup_kernel<<<128, 256, (KCODES * VQ_D + KCODES) * 4>>>(x, cb, out, n);
    vq_reduceA_kernel<<<256, 256>>>(n);
    vq_reduceB_kernel<<<1, 256>>>(out, n);
}

// round 17
// speedup vs baseline: 1.3481x; 1.0808x over previous
#include <cuda_runtime.h>
#include <cuda_fp16.h>
#include <float.h>

#define VQ_D      64
#define KCODES    512
#define M_TILE    64
#define NTHREADS  256
#define NROWS_MAX 524288
#define TAU       2e-2f

typedef unsigned int       u32;
typedef unsigned long long u64;

// ---------------- global scratch (static: no allocation) ----------------
__device__ int    g_flag_count;
__device__ int    g_flag_rows[NROWS_MAX];
__device__ float  g_loss_row[NROWS_MAX];
__device__ double g_partials[256];

// ---------------- smem layout of main kernel (bytes) ----------------
#define SM_BHI   0                        // 512*128 = 65536  B hi fp16, SW128
#define SM_AHI   (SM_BHI + KCODES*128)    // 65536   64*128  A hi
#define SM_ALO   (SM_AHI + M_TILE*128)    // 73728   64*128  A lo
#define SM_EE    (SM_ALO + M_TILE*128)    // 81920   512 f32
#define SM_SB    (SM_EE  + KCODES*4)      // 83968   2*64 f32 best
#define SM_SS    (SM_SB  + 2*M_TILE*4)    // 84480   2*64 f32 second
#define SM_SI    (SM_SS  + 2*M_TILE*4)    // 84992   2*64 i32 idx
#define SM_TOTAL (SM_SI  + 2*M_TILE*4 + 64)   // ~85.6 KB -> 2 CTAs/SM

// ---------------- helpers ----------------
__device__ __forceinline__ u32 smem_u32_base(const void* p) {
    u32 a;
    asm("{ .reg .u64 t; cvta.to.shared.u64 t, %1; cvt.u32.u64 %0, t; }"
        : "=r"(a) : "l"(p));
    return a;
}
// swizzled byte offset for 128B-row tiles (SW128: bits[6:4] ^= bits[9:7])
__device__ __forceinline__ u32 swofs(u32 row, u32 off) {
    u32 b = row * 128u + off;
    return b ^ ((b >> 3) & 0x70u);
}
__device__ __forceinline__ void ldsm_x4(u32& r0, u32& r1, u32& r2, u32& r3, u32 addr) {
    asm volatile("ldmatrix.sync.aligned.m8n8.x4.shared.b16 {%0,%1,%2,%3}, [%4];"
        : "=r"(r0), "=r"(r1), "=r"(r2), "=r"(r3) : "r"(addr));
}
__device__ __forceinline__ void mma16816(float* c, const u32* a, u32 b0, u32 b1) {
    asm volatile("mma.sync.aligned.m16n8k16.row.col.f32.f16.f16.f32 "
        "{%0,%1,%2,%3}, {%4,%5,%6,%7}, {%8,%9}, {%0,%1,%2,%3};"
        : "+f"(c[0]), "+f"(c[1]), "+f"(c[2]), "+f"(c[3])
        : "r"(a[0]), "r"(a[1]), "r"(a[2]), "r"(a[3]), "r"(b0), "r"(b1));
}
// fp16 Dekker split: v = (float)hi + (float)lo + O(2^-22 |v|)
__device__ __forceinline__ void split16(float v, __half& hi, __half& lo) {
    hi = __float2half_rn(v);
    lo = __float2half_rn(v - __half2float(hi));
}
// packed f32x2 (exact replica of the R8 arithmetic for the fixup path)
__device__ __forceinline__ u64 fma2(u64 a, u64 b, u64 c) {
    u64 d;
    asm("fma.rn.f32x2 %0, %1, %2, %3;" : "=l"(d) : "l"(a), "l"(b), "l"(c));
    return d;
}
__device__ __forceinline__ u64 add2(u64 a, u64 b) {
    u64 d;
    asm("add.rn.f32x2 %0, %1, %2;" : "=l"(d) : "l"(a), "l"(b));
    return d;
}
__device__ __forceinline__ float2 u2f(u64 a) {
    float2 r;
    r.x = __uint_as_float((unsigned int)(a & 0xffffffffull));
    r.y = __uint_as_float((unsigned int)(a >> 32));
    return r;
}

// ---------------------------------------------------------------------------
__global__ void vq_init_kernel() { g_flag_count = 0; }

// ---------------------------------------------------------------------------
// Kernel 1: tensor-core score pass, 256 threads, M_TILE=64, 2 CTAs/SM.
//   dot = (a_hi + a_lo) . b_hi  =  x . b_hi   (exact up to fp32 accum)
//   score = ||e||^2 - 2*dot ;  error vs exact score = 2*x.b_lo (std ~2.7e-3)
// Rows whose top-2 margin < TAU=2e-2 (~7.4 sigma) go to the exact fixup.
// Warp layout: 8 warps; wm = w&3 -> rows wm*16..+16; wn = w>>2 -> codes
// wn*256..+256. Per thread: 2 rows (g, g+8 within the 16-row group).
// Two co-resident CTAs overlap each other's gmem/barrier phases.
// ---------------------------------------------------------------------------
__global__ void __launch_bounds__(NTHREADS, 2)
vq_main_kernel(const float* __restrict__ x,
               const float* __restrict__ cb,
               float* __restrict__ out,
               int n)
{
    extern __shared__ char sm[];
    const u32 su  = smem_u32_base(sm);
    const int tid = threadIdx.x;
    const int w   = tid >> 5;
    const int lid = tid & 31;
    const int wm  = w & 3;        // M group: rows wm*16..+16
    const int wn  = w >> 2;       // N half:  codes wn*256..+256

    float* sh_ee = (float*)(sm + SM_EE);
    float* sh_b  = (float*)(sm + SM_SB);
    float* sh_s  = (float*)(sm + SM_SS);
    int*   sh_i  = (int*)  (sm + SM_SI);

    // ---- codebook: B_hi fp16 (SW128) + fp32 ||e||^2 ----
    for (int kk = tid; kk < KCODES; kk += NTHREADS) {
        const float4* e4 = (const float4*)(cb + (size_t)kk * VQ_D);
        float a0 = 0.f, a1 = 0.f, a2 = 0.f, a3 = 0.f;
        #pragma unroll
        for (int j = 0; j < 16; j++) {
            float4 v = e4[j];
            u32 b = swofs((u32)kk, (u32)j * 8u);
            *(__half2*)(sm + SM_BHI + b)     = __halves2half2(__float2half_rn(v.x),
                                                              __float2half_rn(v.y));
            *(__half2*)(sm + SM_BHI + b + 4) = __halves2half2(__float2half_rn(v.z),
                                                              __float2half_rn(v.w));
            a0 = fmaf(v.x, v.x, a0); a1 = fmaf(v.y, v.y, a1);
            a2 = fmaf(v.z, v.z, a2); a3 = fmaf(v.w, v.w, a3);
        }
        sh_ee[kk] = __fadd_rn(__fadd_rn(a0, a1), __fadd_rn(a2, a3));
    }

    // per-lane ldmatrix address components
    const u32 arow = (u32)(lid & 7) + ((u32)(lid >> 3) & 1u) * 8u;
    const u32 aoff = ((u32)(lid >> 4) & 1u) * 16u;
    const u32 brow = (u32)(lid & 7) + ((u32)(lid >> 4) & 1u) * 8u;
    const u32 boff = ((u32)(lid >> 3) & 1u) * 16u;
    const int g = lid >> 2, t = lid & 3;

    // x load/convert mapping: thread -> row tid/4 (0..63), quarter tid&3
    const int pr = tid >> 2, pq = tid & 3;

    const int ntiles = n / M_TILE;

    for (int tile = blockIdx.x; tile < ntiles; tile += gridDim.x) {
        __syncthreads();   // prev-tile smem readers done before overwrite

        // ---- load + split x tile directly from gmem ----
        {
            const float4* xp = (const float4*)(x + ((size_t)tile * M_TILE + pr) * VQ_D + pq * 16);
            #pragma unroll
            for (int j = 0; j < 4; j++) {
                float4 v = xp[j];
                __half h0, h1, h2, h3, l0h, l1h, l2h, l3h;
                split16(v.x, h0, l0h); split16(v.y, h1, l1h);
                split16(v.z, h2, l2h); split16(v.w, h3, l3h);
                u32 b = swofs((u32)pr, (u32)(pq * 32 + j * 8));
                *(__half2*)(sm + SM_AHI + b)     = __halves2half2(h0, h1);
                *(__half2*)(sm + SM_AHI + b + 4) = __halves2half2(h2, h3);
                *(__half2*)(sm + SM_ALO + b)     = __halves2half2(l0h, l1h);
                *(__half2*)(sm + SM_ALO + b + 4) = __halves2half2(l2h, l3h);
            }
        }
        __syncthreads();   // A ready

        // ---- A fragments: this warp's 16 rows (hi & lo), all 4 k-chunks ----
        u32 ahi[4][4], alo[4][4];
        #pragma unroll
        for (int k = 0; k < 4; k++) {
            u32 o = swofs((u32)(wm * 16) + arow, (u32)k * 32u + aoff);
            ldsm_x4(ahi[k][0], ahi[k][1], ahi[k][2], ahi[k][3], su + SM_AHI + o);
            ldsm_x4(alo[k][0], alo[k][1], alo[k][2], alo[k][3], su + SM_ALO + o);
        }

        float best[2] = {FLT_MAX, FLT_MAX};
        float sec [2] = {FLT_MAX, FLT_MAX};
        int   bidx[2] = {0, 0};

        #pragma unroll 1
        for (int chunk = 0; chunk < 4; chunk++) {
            const int nbase = wn * 256 + chunk * 64;
            float acc[8][4];
            #pragma unroll
            for (int j = 0; j < 8; j++)
                #pragma unroll
                for (int q = 0; q < 4; q++) acc[j][q] = 0.f;

            #pragma unroll
            for (int k = 0; k < 4; k++) {
                u32 bh0[8], bh1[8];
                #pragma unroll
                for (int gi = 0; gi < 4; gi++) {
                    u32 o = swofs((u32)(nbase + gi * 16) + brow, (u32)k * 32u + boff);
                    ldsm_x4(bh0[2*gi], bh1[2*gi], bh0[2*gi+1], bh1[2*gi+1], su + SM_BHI + o);
                }
                #pragma unroll
                for (int j = 0; j < 8; j++) {
                    mma16816(acc[j], ahi[k], bh0[j], bh1[j]);  // hi * b_hi
                    mma16816(acc[j], alo[k], bh0[j], bh1[j]);  // lo * b_hi
                }
            }

            // ---- epilogue: score = ee - 2*dot, top-2 tracking (2 rows) ----
            #pragma unroll
            for (int j = 0; j < 8; j++) {
                const int c0 = nbase + j * 8 + 2 * t;
                float2 ee = *(const float2*)(&sh_ee[c0]);
                float d00 = fmaf(acc[j][0], -2.f, ee.x);
                float d01 = fmaf(acc[j][1], -2.f, ee.y);
                float d10 = fmaf(acc[j][2], -2.f, ee.x);
                float d11 = fmaf(acc[j][3], -2.f, ee.y);
                #define UPD(r_, d_, c_) \
                    if ((d_) < best[r_]) { sec[r_] = best[r_]; best[r_] = (d_); bidx[r_] = (c_); } \
                    else sec[r_] = fminf(sec[r_], (d_));
                UPD(0, d00, c0); UPD(0, d01, c0 + 1);
                UPD(1, d10, c0); UPD(1, d11, c0 + 1);
                #undef UPD
            }
        }

        // ---- intra-warp merge over the 4 t-lanes sharing each row ----
        #pragma unroll
        for (int off = 1; off <= 2; off <<= 1) {
            #pragma unroll
            for (int ri = 0; ri < 2; ri++) {
                float ob = __shfl_xor_sync(0xffffffffu, best[ri], off);
                float os = __shfl_xor_sync(0xffffffffu, sec[ri],  off);
                int   oi = __shfl_xor_sync(0xffffffffu, bidx[ri], off);
                bool take = (ob < best[ri]) || (ob == best[ri] && oi < bidx[ri]);
                float loser = take ? best[ri] : ob;
                sec[ri] = fminf(loser, fminf(sec[ri], os));
                if (take) { best[ri] = ob; bidx[ri] = oi; }
            }
        }
        if (t == 0) {
            const int r0 = wm * 16 + g;
            #pragma unroll
            for (int ri = 0; ri < 2; ri++) {
                const int r = r0 + ri * 8;
                sh_b[wn * M_TILE + r] = best[ri];
                sh_s[wn * M_TILE + r] = sec[ri];
                sh_i[wn * M_TILE + r] = bidx[ri];
            }
        }
        __syncthreads();

        // ---- outputs: 256 threads, quarter-row each ----
        {
            const int r = pr, h = pq;
            float b0 = sh_b[r], b1 = sh_b[M_TILE + r];
            float s0 = sh_s[r], s1 = sh_s[M_TILE + r];
            int   i0 = sh_i[r], i1 = sh_i[M_TILE + r];
            bool take = (b1 < b0) || (b1 == b0 && i1 < i0);
            float fb = take ? b1 : b0;
            int   fi = take ? i1 : i0;
            float fs = fminf(take ? b0 : b1, fminf(s0, s1));

            const size_t grow = (size_t)tile * M_TILE + r;
            if (h == 0) {
                if (fs - fb < TAU) {
                    int p = atomicAdd(&g_flag_count, 1);
                    g_flag_rows[p] = (int)grow;
                }
                out[grow] = (float)fi;
            }

            const float4* e4  = (const float4*)(cb + (size_t)fi * VQ_D + h * 16);
            const float4* xr4 = (const float4*)(x + grow * VQ_D + h * 16);
            float4* q4 = (float4*)(out + (size_t)n + grow * VQ_D + h * 16);
            float l0 = 0.f, l1 = 0.f, l2 = 0.f, l3 = 0.f;
            #pragma unroll
            for (int j = 0; j < 4; j++) {
                float4 e = e4[j], xv = xr4[j];
                q4[j] = e;
                float d0 = e.x - xv.x, d1 = e.y - xv.y;
                float d2 = e.z - xv.z, d3 = e.w - xv.w;
                l0 = fmaf(d0, d0, l0); l1 = fmaf(d1, d1, l1);
                l2 = fmaf(d2, d2, l2); l3 = fmaf(d3, d3, l3);
            }
            float part = __fadd_rn(__fadd_rn(l0, l1), __fadd_rn(l2, l3));
            part += __shfl_xor_sync(0xffffffffu, part, 1);
            part += __shfl_xor_sync(0xffffffffu, part, 2);
            if (h == 0) g_loss_row[grow] = part;
        }
        // top-of-loop sync guards smem reuse
    }
}

// ---------------------------------------------------------------------------
// Kernel 2: exact fp32 fixup of flagged rows (bit-identical to the R8 kernel
// arithmetic that passed with zero argmin flips)
// ---------------------------------------------------------------------------
__global__ void __launch_bounds__(256, 1)
vq_fixup_kernel(const float* __restrict__ x,
                const float* __restrict__ cb,
                float* __restrict__ out,
                int n)
{
    if (*(volatile int*)&g_flag_count == 0) return;

    extern __shared__ float sh[];
    float* sh_cb = sh;                 // 512*64
    float* sh_ee = sh + KCODES * VQ_D; // 512

    const int tid = threadIdx.x;
    {
        const float4* cb4 = (const float4*)cb;
        float4* sh4 = (float4*)sh_cb;
        for (int i = tid; i < KCODES * VQ_D / 4; i += 256) sh4[i] = cb4[i];
    }
    __syncthreads();
    for (int kk = tid; kk < KCODES; kk += 256) {
        const float* e = sh_cb + (size_t)kk * VQ_D;
        float a0 = 0.f, a1 = 0.f, a2 = 0.f, a3 = 0.f;
        #pragma unroll
        for (int j = 0; j < VQ_D; j += 4) {
            a0 = fmaf(e[j+0], e[j+0], a0);
            a1 = fmaf(e[j+1], e[j+1], a1);
            a2 = fmaf(e[j+2], e[j+2], a2);
            a3 = fmaf(e[j+3], e[j+3], a3);
        }
        sh_ee[kk] = __fadd_rn(__fadd_rn(a0, a1), __fadd_rn(a2, a3));
    }
    __syncthreads();

    const int count = g_flag_count;
    for (int i = blockIdx.x * 256 + tid; i < count; i += gridDim.x * 256) {
        const int row = g_flag_rows[i];

        u64 xr[VQ_D / 2];
        const ulonglong2* xp = (const ulonglong2*)(x + (size_t)row * VQ_D);
        #pragma unroll
        for (int j = 0; j < VQ_D / 4; j++) {
            ulonglong2 v = xp[j];
            xr[2*j] = v.x; xr[2*j+1] = v.y;
        }
        float xx;
        {
            float a0 = 0.f, a1 = 0.f, a2 = 0.f, a3 = 0.f;
            #pragma unroll
            for (int j = 0; j < VQ_D / 2; j += 2) {
                float2 fa = u2f(xr[j]), fb = u2f(xr[j+1]);
                a0 = fmaf(fa.x, fa.x, a0); a1 = fmaf(fa.y, fa.y, a1);
                a2 = fmaf(fb.x, fb.x, a2); a3 = fmaf(fb.y, fb.y, a3);
            }
            xx = __fadd_rn(__fadd_rn(a0, a1), __fadd_rn(a2, a3));
        }

        float best = 3.402823466e38f;
        int   bi   = 0;
        const ulonglong2* ebase = (const ulonglong2*)sh_cb;
        #pragma unroll 2
        for (int kk = 0; kk < KCODES; kk++) {
            const ulonglong2* e = ebase + (size_t)kk * (VQ_D / 4);
            u64 a0 = 0ull, a1 = 0ull, a2 = 0ull, a3 = 0ull;
            #pragma unroll
            for (int j = 0; j < VQ_D / 4; j += 2) {
                ulonglong2 e0 = e[j];
                ulonglong2 e1 = e[j + 1];
                a0 = fma2(e0.x, xr[2*j    ], a0);
                a1 = fma2(e0.y, xr[2*j + 1], a1);
                a2 = fma2(e1.x, xr[2*j + 2], a2);
                a3 = fma2(e1.y, xr[2*j + 3], a3);
            }
            u64 s = add2(add2(a0, a1), add2(a2, a3));
            float2 sf = u2f(s);
            float dot  = __fadd_rn(sf.x, sf.y);
            float dist = __fadd_rn(__fadd_rn(xx, sh_ee[kk]),
                                   -__fmul_rn(2.0f, dot));
            if (dist < best) { best = dist; bi = kk; }
        }

        out[row] = (float)bi;
        const float*  e  = sh_cb + (size_t)bi * VQ_D;
        const float4* e4 = (const float4*)e;
        float4* q4 = (float4*)(out + (size_t)n + (size_t)row * VQ_D);
        #pragma unroll
        for (int j = 0; j < VQ_D / 4; j++) q4[j] = e4[j];

        float l0 = 0.f, l1 = 0.f, l2 = 0.f, l3 = 0.f;
        #pragma unroll
        for (int j2 = 0; j2 < VQ_D / 2; j2 += 2) {
            float2 fa = u2f(xr[j2]), fb = u2f(xr[j2 + 1]);
            float d0 = e[2*j2 + 0] - fa.x;
            float d1 = e[2*j2 + 1] - fa.y;
            float d2 = e[2*j2 + 2] - fb.x;
            float d3 = e[2*j2 + 3] - fb.y;
            l0 = fmaf(d0, d0, l0); l1 = fmaf(d1, d1, l1);
            l2 = fmaf(d2, d2, l2); l3 = fmaf(d3, d3, l3);
        }
        g_loss_row[row] = __fadd_rn(__fadd_rn(l0, l1), __fadd_rn(l2, l3));
    }
}

// ---------------------------------------------------------------------------
// Kernels 3+4: deterministic staged loss reduction
// ---------------------------------------------------------------------------
__global__ void vq_reduceA_kernel(int n)
{
    __shared__ double shd[256];
    const int base = blockIdx.x * 2048;
    double s = 0.0;
    #pragma unroll
    for (int j = 0; j < 8; j++) {
        int idx = base + j * 256 + threadIdx.x;
        s += (idx < n) ? (double)g_loss_row[idx] : 0.0;
    }
    shd[threadIdx.x] = s;
    __syncthreads();
    for (int off = 128; off > 0; off >>= 1) {
        if (threadIdx.x < off) shd[threadIdx.x] += shd[threadIdx.x + off];
        __syncthreads();
    }
    if (threadIdx.x == 0) g_partials[blockIdx.x] = shd[0];
}

__global__ void vq_reduceB_kernel(float* __restrict__ out, int n)
{
    __shared__ double shd[256];
    shd[threadIdx.x] = g_partials[threadIdx.x];
    __syncthreads();
    for (int off = 128; off > 0; off >>= 1) {
        if (threadIdx.x < off) shd[threadIdx.x] += shd[threadIdx.x + off];
        __syncthreads();
    }
    if (threadIdx.x == 0) {
        double mean = shd[0] / ((double)n * (double)VQ_D);
        out[(size_t)n + (size_t)n * VQ_D] = (float)(mean * 1.25);
    }
}

// ---------------------------------------------------------------------------
extern "C" void kernel_launch(void* const* d_in, const int* in_sizes, int n_in,
                              void* d_out, int out_size)
{
    const float* x  = (const float*)d_in[0];
    const float* cb = (const float*)d_in[1];
    float* out = (float*)d_out;

    const int n = in_sizes[0] / VQ_D;      // 524288
    const int ntiles = n / M_TILE;         // 8192
    int grid = ntiles < 296 ? ntiles : 296;   // 2 CTAs per SM

    static int attr_done = 0;
    if (!attr_done) {
        cudaFuncSetAttribute(vq_main_kernel,
                             cudaFuncAttributeMaxDynamicSharedMemorySize, SM_TOTAL);
        cudaFuncSetAttribute(vq_fixup_kernel,
                             cudaFuncAttributeMaxDynamicSharedMemorySize,
                             (KCODES * VQ_D + KCODES) * 4);
        attr_done = 1;
    }

    vq_init_kernel<<<1, 1>>>();
    vq_main_kernel<<<grid, NTHREADS, SM_TOTAL>>>(x, cb, out, n);
    vq_fixup_kernel<<<128, 256, (KCODES * VQ_D + KCODES) * 4>>>(x, cb, out, n);
    vq_reduceA_kernel<<<256, 256>>>(n);
    vq_reduceB_kernel<<<1, 256>>>(out, n);
}